// round 2
// baseline (speedup 1.0000x reference)
#include <cuda_runtime.h>
#include <math.h>

#define B_ 32
#define S_ 2048
#define H_ 1024
#define NROWS (2 * B_ * S_)   // 131072
#define WARPS_PER_BLOCK 8
#define DOT_BLOCKS (148 * 6)  // exact residency: 6 blocks/SM @ 40 regs, 256 thr

// Scratch (allowed: __device__ globals, no allocation)
__device__ float    g_rewards[NROWS];
__device__ float    g_per_pair[B_];
__device__ int      g_accflag[B_];
__device__ unsigned g_done;

__device__ __forceinline__ float warp_sum(float v) {
#pragma unroll
    for (int o = 16; o; o >>= 1) v += __shfl_xor_sync(0xffffffffu, v, o);
    return v;
}
__device__ __forceinline__ int warp_sum_i(int v) {
#pragma unroll
    for (int o = 16; o; o >>= 1) v += __shfl_xor_sync(0xffffffffu, v, o);
    return v;
}

// ---------------------------------------------------------------------------
// Kernel 1: rewards[row] = dot(hidden[row, :], w)
// Persistent grid-stride: one warp loops over rows; 8 independent float4
// streaming loads per row. Exactly one wave -> no wave-transition cost.
// Also resets g_done for the fused finalize in pair_kernel (graph replay safe:
// this kernel runs strictly before pair_kernel each launch).
// ---------------------------------------------------------------------------
__global__ void __launch_bounds__(WARPS_PER_BLOCK * 32, 6)
reward_dot_kernel(const float* __restrict__ hs, const float* __restrict__ w) {
    if (blockIdx.x == 0 && threadIdx.x == 0) g_done = 0;

    __shared__ float4 sw[H_ / 4];
    for (int i = threadIdx.x; i < H_ / 4; i += blockDim.x)
        sw[i] = reinterpret_cast<const float4*>(w)[i];
    __syncthreads();

    const int warp   = threadIdx.x >> 5;
    const int lane   = threadIdx.x & 31;
    const int gwarp  = blockIdx.x * WARPS_PER_BLOCK + warp;
    const int nwarps = gridDim.x * WARPS_PER_BLOCK;

    // preload w fragment for this lane into registers (reused every row)
    float4 wreg[8];
#pragma unroll
    for (int i = 0; i < 8; i++) wreg[i] = sw[lane + i * 32];

    for (int row = gwarp; row < NROWS; row += nwarps) {
        const float4* __restrict__ hp =
            reinterpret_cast<const float4*>(hs + (size_t)row * H_);
        float acc = 0.0f;
#pragma unroll
        for (int i = 0; i < 8; i++) {
            float4 h = __ldcs(&hp[lane + i * 32]);   // streaming: evict-first
            acc += h.x * wreg[i].x + h.y * wreg[i].y
                 + h.z * wreg[i].z + h.w * wreg[i].w;
        }
        acc = warp_sum(acc);
        if (lane == 0) g_rewards[row] = acc;
    }
}

// ---------------------------------------------------------------------------
// Kernel 2: per-pair index scan + masked sums + fused final reduction.
// One block per pair (B_=32). Last block to finish does loss/acc.
// ---------------------------------------------------------------------------
__global__ void __launch_bounds__(256)
pair_kernel(const int* __restrict__ ids, float* __restrict__ out) {
    const int b   = blockIdx.x;
    const int tid = threadIdx.x;
    const int4*   __restrict__ idc = reinterpret_cast<const int4*>(ids + (size_t)b * S_);
    const int4*   __restrict__ idr = reinterpret_cast<const int4*>(ids + (size_t)(B_ + b) * S_);
    const float*  __restrict__ rwc = g_rewards + (size_t)b * S_;
    const float*  __restrict__ rwr = g_rewards + (size_t)(B_ + b) * S_;

    __shared__ int sc, sr, sd;
    if (tid == 0) { sc = S_; sr = S_; sd = S_; }
    __syncthreads();

    int cmin = S_, rmin = S_, dmin = S_;
#pragma unroll
    for (int it = 0; it < S_ / 4 / 256; it++) {       // 2 iterations
        int v = tid + it * 256;                       // int4 index
        int4 c4 = idc[v], r4 = idr[v];
        int s = v * 4;
        if (c4.x == 0 && s + 0 < cmin) cmin = s + 0;
        if (c4.y == 0 && s + 1 < cmin) cmin = s + 1;
        if (c4.z == 0 && s + 2 < cmin) cmin = s + 2;
        if (c4.w == 0 && s + 3 < cmin) cmin = s + 3;
        if (r4.x == 0 && s + 0 < rmin) rmin = s + 0;
        if (r4.y == 0 && s + 1 < rmin) rmin = s + 1;
        if (r4.z == 0 && s + 2 < rmin) rmin = s + 2;
        if (r4.w == 0 && s + 3 < rmin) rmin = s + 3;
        if (c4.x != r4.x && s + 0 < dmin) dmin = s + 0;
        if (c4.y != r4.y && s + 1 < dmin) dmin = s + 1;
        if (c4.z != r4.z && s + 2 < dmin) dmin = s + 2;
        if (c4.w != r4.w && s + 3 < dmin) dmin = s + 3;
    }
    atomicMin(&sc, cmin);
    atomicMin(&sr, rmin);
    atomicMin(&sd, dmin);
    __syncthreads();

    const int  c_ind     = sc;
    const int  r_ind_pad = sr;
    const bool has_div   = sd < S_;
    const int  div_ind   = has_div ? sd : (S_ - 1);
    const int  r_ind     = has_div ? r_ind_pad : c_ind;
    const int  end_ind   = has_div ? max(c_ind, r_ind_pad) : S_;

    float lsum = 0.0f, csum = 0.0f, rsum = 0.0f;
    int   cnt_local = 0;
    for (int s = div_ind + tid; s < end_ind; s += 256) {
        float rc = rwc[s], rr = rwr[s];
        float x  = rc - rr;
        // log_sigmoid(x) = min(x,0) - log1p(exp(-|x|))
        lsum += fminf(x, 0.0f) - log1pf(__expf(-fabsf(x)));
        csum += __fdividef(1.0f, 1.0f + __expf(-rc));
        rsum += __fdividef(1.0f, 1.0f + __expf(-rr));
        cnt_local++;
    }

    __shared__ float sl[8], ss1[8], ss2[8];
    __shared__ int   sn[8];
    const int warp = tid >> 5, lane = tid & 31;
    float wl = warp_sum(lsum), wc = warp_sum(csum), wr = warp_sum(rsum);
    int   wn = warp_sum_i(cnt_local);
    if (lane == 0) { sl[warp] = wl; ss1[warp] = wc; ss2[warp] = wr; sn[warp] = wn; }
    __syncthreads();

    __shared__ bool s_last;
    if (tid == 0) {
        float L = 0, C = 0, R = 0; int N = 0;
#pragma unroll
        for (int i = 0; i < 8; i++) { L += sl[i]; C += ss1[i]; R += ss2[i]; N += sn[i]; }
        float cnt = fmaxf((float)N, 1.0f);
        g_per_pair[b] = L / cnt;
        g_accflag[b]  = ((C - R) / cnt > 0.5f) ? 1 : 0;
        int ci = c_ind - 1; if (ci < 0) ci = 0; if (ci >= S_) ci = S_ - 1;
        int ri = r_ind - 1; if (ri < 0) ri = 0; if (ri >= S_) ri = S_ - 1;
        out[2 + b]      = rwc[ci];   // chosen_mean_score
        out[2 + B_ + b] = rwr[ri];   // rejected_mean_score
        __threadfence();
        unsigned prev = atomicAdd(&g_done, 1u);
        s_last = (prev == (unsigned)(B_ - 1));
    }
    __syncthreads();

    // Last block finished: deterministic final reduction (fixed order, warp 0)
    if (s_last && tid < 32) {
        float pp = g_per_pair[tid];
        int   af = g_accflag[tid];
        float ls = warp_sum(pp);
        int   ac = warp_sum_i(af);
        if (tid == 0) {
            out[0] = -ls;          // loss
            out[1] = (float)ac;    // acc
        }
    }
}

// ---------------------------------------------------------------------------
extern "C" void kernel_launch(void* const* d_in, const int* in_sizes, int n_in,
                              void* d_out, int out_size) {
    const int*   ids = (const int*)d_in[0];     // input_ids  (2B, S) int32
    const float* hs  = (const float*)d_in[1];   // hidden     (2B, S, H) f32
    const float* w   = (const float*)d_in[2];   // w          (H,) f32
    float* out = (float*)d_out;

    reward_dot_kernel<<<DOT_BLOCKS, WARPS_PER_BLOCK * 32>>>(hs, w);
    pair_kernel<<<B_, 256>>>(ids, out);
}

// round 3
// speedup vs baseline: 1.1042x; 1.1042x over previous
#include <cuda_runtime.h>
#include <math.h>

#define B_ 32
#define S_ 2048
#define H_ 1024
#define NROWS (2 * B_ * S_)   // 131072
#define WARPS_PER_BLOCK 8

// Scratch (allowed: __device__ globals, no allocation)
__device__ float    g_rewards[NROWS];
__device__ float    g_per_pair[B_];
__device__ int      g_accflag[B_];
__device__ unsigned g_done;

__device__ __forceinline__ float warp_sum(float v) {
#pragma unroll
    for (int o = 16; o; o >>= 1) v += __shfl_xor_sync(0xffffffffu, v, o);
    return v;
}
__device__ __forceinline__ int warp_sum_i(int v) {
#pragma unroll
    for (int o = 16; o; o >>= 1) v += __shfl_xor_sync(0xffffffffu, v, o);
    return v;
}
__device__ __forceinline__ int warp_min_i(int v) {
#pragma unroll
    for (int o = 16; o; o >>= 1) v = min(v, __shfl_xor_sync(0xffffffffu, v, o));
    return v;
}

// ---------------------------------------------------------------------------
// Kernel 1: rewards[row] = dot(hidden[row, :], w)   (HBM-bound, 512 MB read)
// One warp per row, flat grid (R1 form: measured 80.3us @ 85.3% DRAM).
// Also resets g_done for the fused finalize in pair_kernel.
// ---------------------------------------------------------------------------
__global__ void __launch_bounds__(WARPS_PER_BLOCK * 32)
reward_dot_kernel(const float* __restrict__ hs, const float* __restrict__ w) {
    if (blockIdx.x == 0 && threadIdx.x == 0) g_done = 0;

    __shared__ float4 sw[H_ / 4];
    for (int i = threadIdx.x; i < H_ / 4; i += blockDim.x)
        sw[i] = reinterpret_cast<const float4*>(w)[i];
    __syncthreads();

    const int warp = threadIdx.x >> 5;
    const int lane = threadIdx.x & 31;
    const int row  = blockIdx.x * WARPS_PER_BLOCK + warp;
    if (row >= NROWS) return;

    const float4* __restrict__ hp =
        reinterpret_cast<const float4*>(hs + (size_t)row * H_);

    float acc = 0.0f;
#pragma unroll
    for (int i = 0; i < 8; i++) {
        float4 h  = __ldcs(&hp[lane + i * 32]);   // streaming: no reuse
        float4 ww = sw[lane + i * 32];
        acc += h.x * ww.x + h.y * ww.y + h.z * ww.z + h.w * ww.w;
    }
    acc = warp_sum(acc);
    if (lane == 0) g_rewards[row] = acc;
}

// ---------------------------------------------------------------------------
// Kernel 2: per-pair scan + masked sums + fused final reduction.
// One block of 1024 threads per pair. Phase 1 splits warps:
//   warps 0-15  : int4 id scan (cmin/rmin/dmin)
//   warps 16-31 : stage both reward rows into smem (coalesced float4)
// Phase 2: masked sums from smem (<=2 iters/thread).
// ---------------------------------------------------------------------------
__global__ void __launch_bounds__(1024)
pair_kernel(const int* __restrict__ ids, float* __restrict__ out) {
    const int b    = blockIdx.x;
    const int tid  = threadIdx.x;
    const int warp = tid >> 5;
    const int lane = tid & 31;

    __shared__ float s_rc[S_];
    __shared__ float s_rr[S_];
    __shared__ int   sc, sr, sd;
    __shared__ float sl[32], ss1[32], ss2[32];
    __shared__ int   sn[32];

    if (tid == 0) { sc = S_; sr = S_; sd = S_; }

    if (warp < 16) {
        // --- id scan: 512 threads, one int4 from each sequence ---
        const int4* __restrict__ idc =
            reinterpret_cast<const int4*>(ids + (size_t)b * S_);
        const int4* __restrict__ idr =
            reinterpret_cast<const int4*>(ids + (size_t)(B_ + b) * S_);
        const int v = tid;               // 0..511
        int4 c4 = idc[v], r4 = idr[v];
        const int s = v * 4;
        int cmin = S_, rmin = S_, dmin = S_;
        if (c4.w == 0) cmin = s + 3;
        if (c4.z == 0) cmin = s + 2;
        if (c4.y == 0) cmin = s + 1;
        if (c4.x == 0) cmin = s + 0;
        if (r4.w == 0) rmin = s + 3;
        if (r4.z == 0) rmin = s + 2;
        if (r4.y == 0) rmin = s + 1;
        if (r4.x == 0) rmin = s + 0;
        if (c4.w != r4.w) dmin = s + 3;
        if (c4.z != r4.z) dmin = s + 2;
        if (c4.y != r4.y) dmin = s + 1;
        if (c4.x != r4.x) dmin = s + 0;
        cmin = warp_min_i(cmin);
        rmin = warp_min_i(rmin);
        dmin = warp_min_i(dmin);
        if (lane == 0) {
            if (cmin < S_) atomicMin(&sc, cmin);
            if (rmin < S_) atomicMin(&sr, rmin);
            if (dmin < S_) atomicMin(&sd, dmin);
        }
    } else {
        // --- reward staging: 512 threads, 2 float4 each (both rows) ---
        const float4* __restrict__ rc4 =
            reinterpret_cast<const float4*>(g_rewards + (size_t)b * S_);
        const float4* __restrict__ rr4 =
            reinterpret_cast<const float4*>(g_rewards + (size_t)(B_ + b) * S_);
        const int v = tid - 512;         // 0..511
        reinterpret_cast<float4*>(s_rc)[v] = rc4[v];
        reinterpret_cast<float4*>(s_rr)[v] = rr4[v];
    }
    __syncthreads();

    const int  c_ind     = sc;
    const int  r_ind_pad = sr;
    const bool has_div   = sd < S_;
    const int  div_ind   = has_div ? sd : (S_ - 1);
    const int  r_ind     = has_div ? r_ind_pad : c_ind;
    const int  end_ind   = has_div ? max(c_ind, r_ind_pad) : S_;

    float lsum = 0.0f, csum = 0.0f, rsum = 0.0f;
    int   cnt_local = 0;
    for (int s = div_ind + tid; s < end_ind; s += 1024) {
        float rc = s_rc[s], rr = s_rr[s];
        float x  = rc - rr;
        // log_sigmoid(x) = min(x,0) - log1p(exp(-|x|))
        lsum += fminf(x, 0.0f) - log1pf(__expf(-fabsf(x)));
        csum += __fdividef(1.0f, 1.0f + __expf(-rc));
        rsum += __fdividef(1.0f, 1.0f + __expf(-rr));
        cnt_local++;
    }

    float wl = warp_sum(lsum), wc = warp_sum(csum), wr = warp_sum(rsum);
    int   wn = warp_sum_i(cnt_local);
    if (lane == 0) { sl[warp] = wl; ss1[warp] = wc; ss2[warp] = wr; sn[warp] = wn; }
    __syncthreads();

    __shared__ bool s_last;
    if (tid == 0) {
        float L = 0, C = 0, R = 0; int N = 0;
#pragma unroll
        for (int i = 0; i < 32; i++) { L += sl[i]; C += ss1[i]; R += ss2[i]; N += sn[i]; }
        float cnt = fmaxf((float)N, 1.0f);
        g_per_pair[b] = L / cnt;
        g_accflag[b]  = ((C - R) / cnt > 0.5f) ? 1 : 0;
        int ci = c_ind - 1; if (ci < 0) ci = 0; if (ci >= S_) ci = S_ - 1;
        int ri = r_ind - 1; if (ri < 0) ri = 0; if (ri >= S_) ri = S_ - 1;
        out[2 + b]      = s_rc[ci];   // chosen_mean_score
        out[2 + B_ + b] = s_rr[ri];   // rejected_mean_score
        __threadfence();
        unsigned prev = atomicAdd(&g_done, 1u);
        s_last = (prev == (unsigned)(B_ - 1));
    }
    __syncthreads();

    // Last block to finish: deterministic final reduction (fixed order)
    if (s_last && tid < 32) {
        float pp = g_per_pair[tid];
        int   af = g_accflag[tid];
        float ls = warp_sum(pp);
        int   ac = warp_sum_i(af);
        if (tid == 0) {
            out[0] = -ls;          // loss
            out[1] = (float)ac;    // acc
        }
    }
}

// ---------------------------------------------------------------------------
extern "C" void kernel_launch(void* const* d_in, const int* in_sizes, int n_in,
                              void* d_out, int out_size) {
    const int*   ids = (const int*)d_in[0];     // input_ids  (2B, S) int32
    const float* hs  = (const float*)d_in[1];   // hidden     (2B, S, H) f32
    const float* w   = (const float*)d_in[2];   // w          (H,) f32
    float* out = (float*)d_out;

    const int blocks = NROWS / WARPS_PER_BLOCK;   // 16384
    reward_dot_kernel<<<blocks, WARPS_PER_BLOCK * 32>>>(hs, w);
    pair_kernel<<<B_, 1024>>>(ids, out);
}